// round 1
// baseline (speedup 1.0000x reference)
#include <cuda_runtime.h>
#include <cuda_bf16.h>
#include <math.h>

// Problem sizes (fixed by the reference)
#define BATCH 8
#define SEQ   2048
#define DIM   512

// Scratch (allocation-free: __device__ globals)
__device__ float g_xw[(size_t)BATCH * SEQ * DIM];                 // 32 MB
__device__ float g_prod[(size_t)BATCH * SEQ * SEQ];               // 128 MB

// ---------------- SGEMM: 128x128 tile, BK=16, 256 threads, 8x8 microtile ----
#define BM 128
#define BN 128
#define BK 16
#define TM 8
#define TN 8

// BT=false: C[M,N] = alpha * A[M,K] @ B[K,N]   (both row-major, NN)
// BT=true : C[M,N] = alpha * A[M,K] @ B[N,K]^T (row-major, NT)
template <bool BT>
__global__ __launch_bounds__(256, 2)
void sgemm_kernel(const float* __restrict__ A, const float* __restrict__ B,
                  float* __restrict__ C, int M, int N, int K,
                  long long strideA, long long strideB, long long strideC,
                  float alpha)
{
    const int b = blockIdx.z;
    A += (long long)b * strideA;
    B += (long long)b * strideB;
    C += (long long)b * strideC;

    __shared__ float As[BK][BM];
    __shared__ float Bs[BK][BN];

    const int tid = threadIdx.x;          // 0..255
    const int tx  = tid & 15;             // 0..15 (N direction)
    const int ty  = tid >> 4;             // 0..15 (M direction)
    const int row0 = blockIdx.y * BM;
    const int col0 = blockIdx.x * BN;

    float acc[TM][TN];
#pragma unroll
    for (int i = 0; i < TM; i++)
#pragma unroll
        for (int j = 0; j < TN; j++) acc[i][j] = 0.f;

    for (int k0 = 0; k0 < K; k0 += BK) {
        // ---- load A tile (BM x BK), store transposed As[k][m] ----
        // 128*16 = 2048 floats = 512 float4; 256 threads x 2
#pragma unroll
        for (int i = 0; i < 2; i++) {
            int l = tid + i * 256;
            int r = l >> 2;               // row within tile (0..127)
            int c = (l & 3) << 2;         // k within tile (0,4,8,12)
            float4 v = *reinterpret_cast<const float4*>(
                &A[(long long)(row0 + r) * K + k0 + c]);
            As[c + 0][r] = v.x; As[c + 1][r] = v.y;
            As[c + 2][r] = v.z; As[c + 3][r] = v.w;
        }
        // ---- load B tile ----
        if (BT) {
            // B is N x K: rows col0..col0+127, cols k0..k0+15 -> Bs[k][n]
#pragma unroll
            for (int i = 0; i < 2; i++) {
                int l = tid + i * 256;
                int r = l >> 2;
                int c = (l & 3) << 2;
                float4 v = *reinterpret_cast<const float4*>(
                    &B[(long long)(col0 + r) * K + k0 + c]);
                Bs[c + 0][r] = v.x; Bs[c + 1][r] = v.y;
                Bs[c + 2][r] = v.z; Bs[c + 3][r] = v.w;
            }
        } else {
            // B is K x N: rows k0..k0+15, cols col0..col0+127 -> Bs[k][n]
#pragma unroll
            for (int i = 0; i < 2; i++) {
                int l = tid + i * 256;
                int r = l >> 5;               // k row (0..15)
                int c = (l & 31) << 2;        // n col (0..124 step 4)
                float4 v = *reinterpret_cast<const float4*>(
                    &B[(long long)(k0 + r) * N + col0 + c]);
                *reinterpret_cast<float4*>(&Bs[r][c]) = v;
            }
        }
        __syncthreads();

#pragma unroll
        for (int k = 0; k < BK; k++) {
            float af[TM], bf[TN];
#pragma unroll
            for (int i = 0; i < TM; i++) af[i] = As[k][ty * TM + i];
#pragma unroll
            for (int j = 0; j < TN; j++) bf[j] = Bs[k][tx * TN + j];
#pragma unroll
            for (int i = 0; i < TM; i++)
#pragma unroll
                for (int j = 0; j < TN; j++)
                    acc[i][j] = fmaf(af[i], bf[j], acc[i][j]);
        }
        __syncthreads();
    }

    // ---- epilogue ----
#pragma unroll
    for (int i = 0; i < TM; i++) {
        long long r = row0 + ty * TM + i;
#pragma unroll
        for (int j = 0; j < TN; j += 4) {
            float4 v = make_float4(acc[i][j + 0] * alpha, acc[i][j + 1] * alpha,
                                   acc[i][j + 2] * alpha, acc[i][j + 3] * alpha);
            *reinterpret_cast<float4*>(&C[r * N + col0 + tx * TN + j]) = v;
        }
    }
}

// ---------------- row softmax over 2048 cols, in place ----------------------
__global__ __launch_bounds__(256)
void softmax2048_kernel(float* __restrict__ P)
{
    long long row = blockIdx.x;
    float* p = P + row * (long long)SEQ;
    const int tid = threadIdx.x;

    float4* p4 = reinterpret_cast<float4*>(p);
    float4 v0 = p4[tid];
    float4 v1 = p4[tid + 256];

    float m = fmaxf(fmaxf(fmaxf(v0.x, v0.y), fmaxf(v0.z, v0.w)),
                    fmaxf(fmaxf(v1.x, v1.y), fmaxf(v1.z, v1.w)));
#pragma unroll
    for (int o = 16; o; o >>= 1) m = fmaxf(m, __shfl_xor_sync(0xffffffffu, m, o));

    __shared__ float smax[8];
    __shared__ float ssum[8];
    const int w = tid >> 5, lane = tid & 31;
    if (lane == 0) smax[w] = m;
    __syncthreads();
    float mm = smax[0];
#pragma unroll
    for (int i = 1; i < 8; i++) mm = fmaxf(mm, smax[i]);

    v0.x = __expf(v0.x - mm); v0.y = __expf(v0.y - mm);
    v0.z = __expf(v0.z - mm); v0.w = __expf(v0.w - mm);
    v1.x = __expf(v1.x - mm); v1.y = __expf(v1.y - mm);
    v1.z = __expf(v1.z - mm); v1.w = __expf(v1.w - mm);

    float s = (v0.x + v0.y + v0.z + v0.w) + (v1.x + v1.y + v1.z + v1.w);
#pragma unroll
    for (int o = 16; o; o >>= 1) s += __shfl_xor_sync(0xffffffffu, s, o);
    if (lane == 0) ssum[w] = s;
    __syncthreads();
    float ss = ssum[0];
#pragma unroll
    for (int i = 1; i < 8; i++) ss += ssum[i];
    float inv = __frcp_rn(ss);

    v0.x *= inv; v0.y *= inv; v0.z *= inv; v0.w *= inv;
    v1.x *= inv; v1.y *= inv; v1.z *= inv; v1.w *= inv;
    p4[tid] = v0;
    p4[tid + 256] = v1;
}

extern "C" void kernel_launch(void* const* d_in, const int* in_sizes, int n_in,
                              void* d_out, int out_size)
{
    const float* x = (const float*)d_in[0];        // [B, S, D]
    const float* W = (const float*)d_in[1];        // [D, D]
    float* out = (float*)d_out;                    // [B, S, D]

    float* xw;
    float* prod;
    cudaGetSymbolAddress((void**)&xw, g_xw);
    cudaGetSymbolAddress((void**)&prod, g_prod);

    const float inv_sqrt_d = 0.04419417382415922f;  // 1/sqrt(512)

    // GEMM1: xw = x @ W   (M=16384, N=512, K=512, NN)
    {
        dim3 grid(DIM / BN, (BATCH * SEQ) / BM, 1);
        sgemm_kernel<false><<<grid, 256>>>(x, W, xw,
                                           BATCH * SEQ, DIM, DIM,
                                           0, 0, 0, 1.0f);
    }
    // GEMM2: prod[b] = (xw[b] @ x[b]^T) / sqrt(D)   (M=N=2048, K=512, NT)
    {
        dim3 grid(SEQ / BN, SEQ / BM, BATCH);
        sgemm_kernel<true><<<grid, 256>>>(xw, x, prod,
                                          SEQ, SEQ, DIM,
                                          (long long)SEQ * DIM,
                                          (long long)SEQ * DIM,
                                          (long long)SEQ * SEQ,
                                          inv_sqrt_d);
    }
    // Softmax rows (in place)
    softmax2048_kernel<<<BATCH * SEQ, 256>>>(prod);

    // GEMM3: out[b] = prod[b] @ x[b]   (M=2048, N=512, K=2048, NN)
    {
        dim3 grid(DIM / BN, SEQ / BM, BATCH);
        sgemm_kernel<false><<<grid, 256>>>(prod, x, out,
                                           SEQ, DIM, SEQ,
                                           (long long)SEQ * SEQ,
                                           (long long)SEQ * DIM,
                                           (long long)SEQ * DIM,
                                           1.0f);
    }
}

// round 4
// speedup vs baseline: 1.3769x; 1.3769x over previous
#include <cuda_runtime.h>
#include <cstdint>

#define BATCH 8
#define SEQ   2048
#define DIM   512

// ---------------- scratch (allocation-free) ----------------
__device__ float g_xw[(size_t)BATCH * SEQ * DIM];    // 32 MB
__device__ float g_prod[(size_t)BATCH * SEQ * SEQ];  // 128 MB
__device__ float g_wt[(size_t)DIM * DIM];            // 1 MB  (W^T)
__device__ float g_xt[(size_t)BATCH * SEQ * DIM];    // 32 MB (x^T per batch)

// ---------------- helpers ----------------
__device__ __forceinline__ uint32_t smem_u32(const void* p) {
    uint32_t a;
    asm("{ .reg .u64 t; cvta.to.shared.u64 t, %1; cvt.u32.u64 %0, t; }" : "=r"(a) : "l"(p));
    return a;
}
__device__ __forceinline__ void cp_async16(uint32_t dst, const void* src) {
    asm volatile("cp.async.cg.shared.global [%0], [%1], 16;" :: "r"(dst), "l"(src));
}
#define CP_COMMIT() asm volatile("cp.async.commit_group;" ::: "memory")
#define CP_WAIT(n)  asm volatile("cp.async.wait_group %0;" :: "n"(n) : "memory")

#define LDSM4(r, addr) \
    asm volatile("ldmatrix.sync.aligned.m8n8.x4.shared.b16 {%0,%1,%2,%3}, [%4];" \
                 : "=r"((r)[0]), "=r"((r)[1]), "=r"((r)[2]), "=r"((r)[3]) : "r"(addr))

#define MMA_TF32(c, a0, a1, a2, a3, b0, b1) \
    asm volatile("mma.sync.aligned.m16n8k8.row.col.f32.tf32.tf32.f32 " \
                 "{%0,%1,%2,%3}, {%4,%5,%6,%7}, {%8,%9}, {%0,%1,%2,%3};" \
                 : "+f"((c)[0]), "+f"((c)[1]), "+f"((c)[2]), "+f"((c)[3]) \
                 : "r"(a0), "r"(a1), "r"(a2), "r"(a3), "r"(b0), "r"(b1))

// split fp32 -> (hi, lo) tf32 pair: v = hi + lo + O(u^2)
__device__ __forceinline__ void split_tf32(uint32_t raw, uint32_t& hi, uint32_t& lo) {
    float v = __uint_as_float(raw);
    asm("cvt.rna.tf32.f32 %0, %1;" : "=r"(hi) : "f"(v));
    float r = v - __uint_as_float(hi);
    asm("cvt.rna.tf32.f32 %0, %1;" : "=r"(lo) : "f"(r));
}

// ---------------- tf32x3 mma.sync GEMM: C[M,N] = alpha * A[M,K] @ B[N,K]^T ----------------
// BM=BN=128, BK=32 (128-byte SMEM rows, xor-swizzled), 256 threads, 3-stage cp.async.
// fp32 operands split in-register into tf32 hi/lo; 3 MMAs per pair (hi*hi + hi*lo + lo*hi).
#define BM 128
#define BN 128
#define BK 32
#define STAGES 3
#define A_BYTES (BM * 128)                // 16 KB
#define STAGE_BYTES (2 * A_BYTES)         // 32 KB (A + B)
#define GEMM_SMEM (STAGES * STAGE_BYTES)  // 96 KB

__global__ __launch_bounds__(256, 1)
void tf32x3_gemm_nt(const float* __restrict__ A, const float* __restrict__ B,
                    float* __restrict__ C, int M, int N, int K,
                    long long sA, long long sB, long long sC, float alpha)
{
    extern __shared__ char smem[];
    const uint32_t sb = smem_u32(smem);

    const int tid = threadIdx.x, lane = tid & 31, wid = tid >> 5;
    const int wm = wid >> 2;          // 0..1 : 64-row warp block
    const int wn = wid & 3;           // 0..3 : 32-col warp block
    const int b = blockIdx.z;
    A += (long long)b * sA;
    B += (long long)b * sB;
    C += (long long)b * sC;
    const int row0 = blockIdx.y * BM;
    const int col0 = blockIdx.x * BN;

    const int lrow = tid >> 3;        // 0..31, step +32 per round
    const int lseg = tid & 7;         // 16B segment in the 128B row

    const int a_ra = (lane & 7) | (((lane >> 3) & 1) << 3);   // row-in-16
    const int a_ho = (lane >> 4) << 4;                        // 0/16 (k half)
    const int b_ra = (lane & 7) | (((lane >> 4) & 1) << 3);
    const int b_ho = ((lane >> 3) & 1) << 4;

    float acc[4][4][4];
#pragma unroll
    for (int i = 0; i < 4; i++)
#pragma unroll
        for (int j = 0; j < 4; j++)
#pragma unroll
            for (int v = 0; v < 4; v++) acc[i][j][v] = 0.f;

    const int NT = K / BK;

    auto load_tile = [&](int s, int kt) {
        const uint32_t aB = sb + s * STAGE_BYTES;
        const uint32_t bB = aB + A_BYTES;
        const float* Ag = A + (long long)row0 * K + kt * BK;
        const float* Bg = B + (long long)col0 * K + kt * BK;
#pragma unroll
        for (int j = 0; j < 4; j++) {
            int r = lrow + j * 32;
            uint32_t off = (uint32_t)r * 128 + (((uint32_t)lseg * 16) ^ ((r & 7) << 4));
            cp_async16(aB + off, Ag + (long long)r * K + lseg * 4);
        }
#pragma unroll
        for (int j = 0; j < 4; j++) {
            int r = lrow + j * 32;
            uint32_t off = (uint32_t)r * 128 + (((uint32_t)lseg * 16) ^ ((r & 7) << 4));
            cp_async16(bB + off, Bg + (long long)r * K + lseg * 4);
        }
    };

    int kload = 0;
#pragma unroll
    for (int s = 0; s < STAGES - 1; s++) {
        load_tile(s, kload);
        CP_COMMIT();
        kload++;
    }

    for (int kt = 0; kt < NT; kt++) {
        CP_WAIT(STAGES - 2);
        __syncthreads();

        if (kload < NT) {
            load_tile(kload % STAGES, kload);
            CP_COMMIT();
            kload++;
        }

        const int cs = kt % STAGES;
        const uint32_t aB = sb + cs * STAGE_BYTES;
        const uint32_t bB = aB + A_BYTES;

#pragma unroll
        for (int ks = 0; ks < 4; ks++) {
            // ---- B fragments: load + split ----
            uint32_t bhi[2][4], blo[2][4];
#pragma unroll
            for (int p = 0; p < 2; p++) {
                uint32_t braw[4];
                int n = wn * 32 + p * 16 + b_ra;
                uint32_t addr = bB + (uint32_t)n * 128 +
                                (((uint32_t)(b_ho + ks * 32)) ^ ((n & 7) << 4));
                LDSM4(braw, addr);
#pragma unroll
                for (int q = 0; q < 4; q++) split_tf32(braw[q], bhi[p][q], blo[p][q]);
            }
            // ---- A fragments per mt: load + split, then 3x MMA ----
#pragma unroll
            for (int mt = 0; mt < 4; mt++) {
                uint32_t araw[4], ahi[4], alo[4];
                int m = wm * 64 + mt * 16 + a_ra;
                uint32_t addr = aB + (uint32_t)m * 128 +
                                (((uint32_t)(a_ho + ks * 32)) ^ ((m & 7) << 4));
                LDSM4(araw, addr);
#pragma unroll
                for (int q = 0; q < 4; q++) split_tf32(araw[q], ahi[q], alo[q]);
#pragma unroll
                for (int nt = 0; nt < 4; nt++) {
                    const int p = nt >> 1, q0 = (nt & 1) * 2;
                    MMA_TF32(acc[mt][nt], ahi[0], ahi[1], ahi[2], ahi[3],
                             bhi[p][q0], bhi[p][q0 + 1]);
                    MMA_TF32(acc[mt][nt], ahi[0], ahi[1], ahi[2], ahi[3],
                             blo[p][q0], blo[p][q0 + 1]);
                    MMA_TF32(acc[mt][nt], alo[0], alo[1], alo[2], alo[3],
                             bhi[p][q0], bhi[p][q0 + 1]);
                }
            }
        }
    }

    // ---- epilogue ----
    const int g = lane >> 2;
    const int qc = (lane & 3) << 1;
#pragma unroll
    for (int mt = 0; mt < 4; mt++) {
#pragma unroll
        for (int nt = 0; nt < 4; nt++) {
            long long r0 = row0 + wm * 64 + mt * 16 + g;
            int cbase = col0 + wn * 32 + nt * 8 + qc;
            float2 v0 = make_float2(acc[mt][nt][0] * alpha, acc[mt][nt][1] * alpha);
            float2 v1 = make_float2(acc[mt][nt][2] * alpha, acc[mt][nt][3] * alpha);
            *reinterpret_cast<float2*>(&C[r0 * N + cbase]) = v0;
            *reinterpret_cast<float2*>(&C[(r0 + 8) * N + cbase]) = v1;
        }
    }
}

// ---------------- transpose: out[b][c][r] = in[b][r][c] ----------------
__global__ __launch_bounds__(256)
void transpose_kernel(const float* __restrict__ in, float* __restrict__ out, int R, int Ccols)
{
    __shared__ float t[32][33];
    const int b = blockIdx.z;
    in += (long long)b * R * Ccols;
    out += (long long)b * R * Ccols;
    const int r0 = blockIdx.y * 32, c0 = blockIdx.x * 32;
    const int x = threadIdx.x, y = threadIdx.y;
#pragma unroll
    for (int i = 0; i < 32; i += 8)
        t[y + i][x] = in[(long long)(r0 + y + i) * Ccols + c0 + x];
    __syncthreads();
#pragma unroll
    for (int i = 0; i < 32; i += 8)
        out[(long long)(c0 + y + i) * R + r0 + x] = t[x][y + i];
}

// ---------------- row softmax over 2048 cols, in place ----------------
__global__ __launch_bounds__(256)
void softmax2048_kernel(float* __restrict__ P)
{
    long long row = blockIdx.x;
    float* p = P + row * (long long)SEQ;
    const int tid = threadIdx.x;

    float4* p4 = reinterpret_cast<float4*>(p);
    float4 v0 = p4[tid];
    float4 v1 = p4[tid + 256];

    float m = fmaxf(fmaxf(fmaxf(v0.x, v0.y), fmaxf(v0.z, v0.w)),
                    fmaxf(fmaxf(v1.x, v1.y), fmaxf(v1.z, v1.w)));
#pragma unroll
    for (int o = 16; o; o >>= 1) m = fmaxf(m, __shfl_xor_sync(0xffffffffu, m, o));

    __shared__ float smax[8];
    __shared__ float ssum[8];
    const int w = tid >> 5, lane = tid & 31;
    if (lane == 0) smax[w] = m;
    __syncthreads();
    float mm = smax[0];
#pragma unroll
    for (int i = 1; i < 8; i++) mm = fmaxf(mm, smax[i]);

    v0.x = __expf(v0.x - mm); v0.y = __expf(v0.y - mm);
    v0.z = __expf(v0.z - mm); v0.w = __expf(v0.w - mm);
    v1.x = __expf(v1.x - mm); v1.y = __expf(v1.y - mm);
    v1.z = __expf(v1.z - mm); v1.w = __expf(v1.w - mm);

    float s = (v0.x + v0.y + v0.z + v0.w) + (v1.x + v1.y + v1.z + v1.w);
#pragma unroll
    for (int o = 16; o; o >>= 1) s += __shfl_xor_sync(0xffffffffu, s, o);
    if (lane == 0) ssum[w] = s;
    __syncthreads();
    float ss = ssum[0];
#pragma unroll
    for (int i = 1; i < 8; i++) ss += ssum[i];
    float inv = __frcp_rn(ss);

    v0.x *= inv; v0.y *= inv; v0.z *= inv; v0.w *= inv;
    v1.x *= inv; v1.y *= inv; v1.z *= inv; v1.w *= inv;
    p4[tid] = v0;
    p4[tid + 256] = v1;
}

// ---------------- launch ----------------
extern "C" void kernel_launch(void* const* d_in, const int* in_sizes, int n_in,
                              void* d_out, int out_size)
{
    const float* x = (const float*)d_in[0];  // [B, S, D]
    const float* W = (const float*)d_in[1];  // [D, D]
    float* out = (float*)d_out;              // [B, S, D]

    float *xw, *prod, *wt, *xt;
    cudaGetSymbolAddress((void**)&xw, g_xw);
    cudaGetSymbolAddress((void**)&prod, g_prod);
    cudaGetSymbolAddress((void**)&wt, g_wt);
    cudaGetSymbolAddress((void**)&xt, g_xt);

    cudaFuncSetAttribute(tf32x3_gemm_nt, cudaFuncAttributeMaxDynamicSharedMemorySize, GEMM_SMEM);

    const float inv_sqrt_d = 0.04419417382415922f;  // 1/sqrt(512)

    // W^T (GEMM1 NT form) and x^T per batch (GEMM3 NT form)
    transpose_kernel<<<dim3(DIM / 32, DIM / 32, 1), dim3(32, 8)>>>(W, wt, DIM, DIM);
    transpose_kernel<<<dim3(DIM / 32, SEQ / 32, BATCH), dim3(32, 8)>>>(x, xt, SEQ, DIM);

    // GEMM1: xw = x @ W = x @ (W^T)^T    M=16384, N=512, K=512
    tf32x3_gemm_nt<<<dim3(DIM / BN, (BATCH * SEQ) / BM, 1), 256, GEMM_SMEM>>>(
        x, wt, xw, BATCH * SEQ, DIM, DIM, 0, 0, 0, 1.0f);

    // GEMM2: prod[b] = (xw[b] @ x[b]^T) / sqrt(D)   M=N=2048, K=512 (NT natively)
    tf32x3_gemm_nt<<<dim3(SEQ / BN, SEQ / BM, BATCH), 256, GEMM_SMEM>>>(
        xw, x, prod, SEQ, SEQ, DIM,
        (long long)SEQ * DIM, (long long)SEQ * DIM, (long long)SEQ * SEQ, inv_sqrt_d);

    // softmax rows, in place
    softmax2048_kernel<<<BATCH * SEQ, 256>>>(prod);

    // GEMM3: out[b] = prod[b] @ x[b] = prod[b] @ (x[b]^T)^T   M=2048, N=512, K=2048
    tf32x3_gemm_nt<<<dim3(DIM / BN, SEQ / BM, BATCH), 256, GEMM_SMEM>>>(
        prod, xt, out, SEQ, DIM, SEQ,
        (long long)SEQ * SEQ, (long long)SEQ * DIM, (long long)SEQ * DIM, 1.0f);
}

// round 5
// speedup vs baseline: 1.6000x; 1.1620x over previous
#include <cuda_runtime.h>
#include <cstdint>

#define BATCH 8
#define SEQ   2048
#define DIM   512

// ---------------- scratch (allocation-free) ----------------
__device__ float g_xh[(size_t)BATCH * SEQ * DIM];     // x hi
__device__ float g_xl[(size_t)BATCH * SEQ * DIM];     // x lo
__device__ float g_xwh[(size_t)BATCH * SEQ * DIM];    // xw hi
__device__ float g_xwl[(size_t)BATCH * SEQ * DIM];    // xw lo
__device__ float g_prod[(size_t)BATCH * SEQ * SEQ];   // logits, then P hi
__device__ float g_plo[(size_t)BATCH * SEQ * SEQ];    // P lo
__device__ float g_wth[(size_t)DIM * DIM];            // W^T hi
__device__ float g_wtl[(size_t)DIM * DIM];            // W^T lo
__device__ float g_xth[(size_t)BATCH * SEQ * DIM];    // x^T hi
__device__ float g_xtl[(size_t)BATCH * SEQ * DIM];    // x^T lo

// ---------------- helpers ----------------
__device__ __forceinline__ uint32_t smem_u32(const void* p) {
    uint32_t a;
    asm("{ .reg .u64 t; cvta.to.shared.u64 t, %1; cvt.u32.u64 %0, t; }" : "=r"(a) : "l"(p));
    return a;
}
__device__ __forceinline__ void cp_async16(uint32_t dst, const void* src) {
    asm volatile("cp.async.cg.shared.global [%0], [%1], 16;" :: "r"(dst), "l"(src));
}
#define CP_COMMIT() asm volatile("cp.async.commit_group;" ::: "memory")
#define CP_WAIT(n)  asm volatile("cp.async.wait_group %0;" :: "n"(n) : "memory")

#define LDSM4(r, addr) \
    asm volatile("ldmatrix.sync.aligned.m8n8.x4.shared.b16 {%0,%1,%2,%3}, [%4];" \
                 : "=r"((r)[0]), "=r"((r)[1]), "=r"((r)[2]), "=r"((r)[3]) : "r"(addr))

#define MMA_TF32(c, a, b0, b1) \
    asm volatile("mma.sync.aligned.m16n8k8.row.col.f32.tf32.tf32.f32 " \
                 "{%0,%1,%2,%3}, {%4,%5,%6,%7}, {%8,%9}, {%0,%1,%2,%3};" \
                 : "+f"((c)[0]), "+f"((c)[1]), "+f"((c)[2]), "+f"((c)[3]) \
                 : "r"((a)[0]), "r"((a)[1]), "r"((a)[2]), "r"((a)[3]), "r"(b0), "r"(b1))

// split fp32 v -> hi = tf32(v), lo = tf32(v - hi)
__device__ __forceinline__ void split_f(float v, float& hi, float& lo) {
    uint32_t h, l;
    asm("cvt.rna.tf32.f32 %0, %1;" : "=r"(h) : "f"(v));
    float r = v - __uint_as_float(h);
    asm("cvt.rna.tf32.f32 %0, %1;" : "=r"(l) : "f"(r));
    hi = __uint_as_float(h);
    lo = __uint_as_float(l);
}

// ---------------- single-MMA tf32 GEMM over 3 pre-split K-segments ----------------
// C[M,N] = alpha * sum_seg( Aseg[M,K] @ Bseg[N,K]^T )
// segments: (A_hi,B_hi), (A_lo,B_hi), (A_hi,B_lo)  == tf32x3
#define BM 128
#define BN 128
#define BK 32
#define STAGES 3
#define A_BYTES (BM * 128)                // 16 KB
#define STAGE_BYTES (2 * A_BYTES)         // 32 KB
#define GEMM_SMEM (STAGES * STAGE_BYTES)  // 96 KB

__global__ __launch_bounds__(256, 2)
void tf32seg_gemm_nt(const float* __restrict__ Ahi, const float* __restrict__ Alo,
                     const float* __restrict__ Bhi, const float* __restrict__ Blo,
                     float* __restrict__ C, float* __restrict__ Clo,
                     int M, int N, int K, int ksh,
                     long long sA, long long sB, long long sC, float alpha)
{
    extern __shared__ char smem[];
    const uint32_t sb = smem_u32(smem);

    const int tid = threadIdx.x, lane = tid & 31, wid = tid >> 5;
    const int wm = wid >> 2;          // 0..1
    const int wn = wid & 3;           // 0..3
    const int b = blockIdx.z;
    const long long offA = (long long)b * sA;
    const long long offB = (long long)b * sB;
    C += (long long)b * sC;
    if (Clo) Clo += (long long)b * sC;
    const int row0 = blockIdx.y * BM;
    const int col0 = blockIdx.x * BN;

    const int lrow = tid >> 3;
    const int lseg = tid & 7;

    const int a_ra = (lane & 7) | (((lane >> 3) & 1) << 3);
    const int a_ho = (lane >> 4) << 4;
    const int b_ra = (lane & 7) | (((lane >> 4) & 1) << 3);
    const int b_ho = ((lane >> 3) & 1) << 4;

    float acc[4][4][4];
#pragma unroll
    for (int i = 0; i < 4; i++)
#pragma unroll
        for (int j = 0; j < 4; j++)
#pragma unroll
            for (int v = 0; v < 4; v++) acc[i][j][v] = 0.f;

    const int NTk = 1 << ksh;             // K / BK
    const int NT = 3 * NTk;               // virtual tiles over 3 segments
    const int kmask = NTk - 1;

    auto load_tile = [&](int s, int t) {
        const int seg = t >> ksh;
        const int kt = t & kmask;
        // segment pointer select: (hi,hi) (lo,hi) (hi,lo)
        const float* Ap = (seg == 1) ? Alo : Ahi;
        const float* Bp = (seg == 2) ? Blo : Bhi;
        const uint32_t aB = sb + s * STAGE_BYTES;
        const uint32_t bB = aB + A_BYTES;
        const float* Ag = Ap + offA + (long long)row0 * K + kt * BK;
        const float* Bg = Bp + offB + (long long)col0 * K + kt * BK;
#pragma unroll
        for (int j = 0; j < 4; j++) {
            int r = lrow + j * 32;
            uint32_t off = (uint32_t)r * 128 + (((uint32_t)lseg * 16) ^ ((r & 7) << 4));
            cp_async16(aB + off, Ag + (long long)r * K + lseg * 4);
        }
#pragma unroll
        for (int j = 0; j < 4; j++) {
            int r = lrow + j * 32;
            uint32_t off = (uint32_t)r * 128 + (((uint32_t)lseg * 16) ^ ((r & 7) << 4));
            cp_async16(bB + off, Bg + (long long)r * K + lseg * 4);
        }
    };

    int kload = 0;
#pragma unroll
    for (int s = 0; s < STAGES - 1; s++) {
        load_tile(s, kload);
        CP_COMMIT();
        kload++;
    }

    int cs = 0;
    for (int t = 0; t < NT; t++) {
        CP_WAIT(STAGES - 2);
        __syncthreads();

        if (kload < NT) {
            int ls = kload % STAGES;
            load_tile(ls, kload);
            CP_COMMIT();
            kload++;
        }

        const uint32_t aB = sb + cs * STAGE_BYTES;
        const uint32_t bB = aB + A_BYTES;
        cs = (cs + 1 == STAGES) ? 0 : cs + 1;

#pragma unroll
        for (int ks = 0; ks < 4; ks++) {
            uint32_t af[4][4], bf[2][4];
#pragma unroll
            for (int mt = 0; mt < 4; mt++) {
                int m = wm * 64 + mt * 16 + a_ra;
                uint32_t addr = aB + (uint32_t)m * 128 +
                                (((uint32_t)(a_ho + ks * 32)) ^ ((m & 7) << 4));
                LDSM4(af[mt], addr);
            }
#pragma unroll
            for (int p = 0; p < 2; p++) {
                int n = wn * 32 + p * 16 + b_ra;
                uint32_t addr = bB + (uint32_t)n * 128 +
                                (((uint32_t)(b_ho + ks * 32)) ^ ((n & 7) << 4));
                LDSM4(bf[p], addr);
            }
#pragma unroll
            for (int mt = 0; mt < 4; mt++)
#pragma unroll
                for (int nt = 0; nt < 4; nt++)
                    MMA_TF32(acc[mt][nt], af[mt], bf[nt >> 1][(nt & 1) * 2],
                             bf[nt >> 1][(nt & 1) * 2 + 1]);
        }
    }

    // ---- epilogue ----
    const int g = lane >> 2;
    const int qc = (lane & 3) << 1;
#pragma unroll
    for (int mt = 0; mt < 4; mt++) {
#pragma unroll
        for (int nt = 0; nt < 4; nt++) {
            long long r0 = row0 + wm * 64 + mt * 16 + g;
            int cbase = col0 + wn * 32 + nt * 8 + qc;
            float v00 = acc[mt][nt][0] * alpha, v01 = acc[mt][nt][1] * alpha;
            float v10 = acc[mt][nt][2] * alpha, v11 = acc[mt][nt][3] * alpha;
            if (Clo) {
                float h0, l0, h1, l1;
                split_f(v00, h0, l0); split_f(v01, h1, l1);
                *reinterpret_cast<float2*>(&C[r0 * N + cbase]) = make_float2(h0, h1);
                *reinterpret_cast<float2*>(&Clo[r0 * N + cbase]) = make_float2(l0, l1);
                split_f(v10, h0, l0); split_f(v11, h1, l1);
                *reinterpret_cast<float2*>(&C[(r0 + 8) * N + cbase]) = make_float2(h0, h1);
                *reinterpret_cast<float2*>(&Clo[(r0 + 8) * N + cbase]) = make_float2(l0, l1);
            } else {
                *reinterpret_cast<float2*>(&C[r0 * N + cbase]) = make_float2(v00, v01);
                *reinterpret_cast<float2*>(&C[(r0 + 8) * N + cbase]) = make_float2(v10, v11);
            }
        }
    }
}

// ---------------- elementwise split: in -> hi, lo ----------------
__global__ __launch_bounds__(256)
void split_kernel(const float* __restrict__ in, float* __restrict__ hi, float* __restrict__ lo)
{
    int i = blockIdx.x * 256 + threadIdx.x;
    float4 v = reinterpret_cast<const float4*>(in)[i];
    float4 h, l;
    split_f(v.x, h.x, l.x); split_f(v.y, h.y, l.y);
    split_f(v.z, h.z, l.z); split_f(v.w, h.w, l.w);
    reinterpret_cast<float4*>(hi)[i] = h;
    reinterpret_cast<float4*>(lo)[i] = l;
}

// ---------------- transpose + split: outX[b][c][r] = split(in[b][r][c]) ----------------
__global__ __launch_bounds__(256)
void transpose_split_kernel(const float* __restrict__ in, float* __restrict__ hi,
                            float* __restrict__ lo, int R, int Ccols)
{
    __shared__ float t[32][33];
    const int b = blockIdx.z;
    in += (long long)b * R * Ccols;
    hi += (long long)b * R * Ccols;
    lo += (long long)b * R * Ccols;
    const int r0 = blockIdx.y * 32, c0 = blockIdx.x * 32;
    const int x = threadIdx.x, y = threadIdx.y;
#pragma unroll
    for (int i = 0; i < 32; i += 8)
        t[y + i][x] = in[(long long)(r0 + y + i) * Ccols + c0 + x];
    __syncthreads();
#pragma unroll
    for (int i = 0; i < 32; i += 8) {
        float h, l;
        split_f(t[x][y + i], h, l);
        long long o = (long long)(c0 + y + i) * R + r0 + x;
        hi[o] = h;
        lo[o] = l;
    }
}

// ---------------- row softmax over 2048 cols; writes P_hi (in place) + P_lo ----------------
__global__ __launch_bounds__(256)
void softmax2048_kernel(float* __restrict__ P, float* __restrict__ Plo)
{
    long long row = blockIdx.x;
    float* p = P + row * (long long)SEQ;
    float* pl = Plo + row * (long long)SEQ;
    const int tid = threadIdx.x;

    float4* p4 = reinterpret_cast<float4*>(p);
    float4* pl4 = reinterpret_cast<float4*>(pl);
    float4 v0 = p4[tid];
    float4 v1 = p4[tid + 256];

    float m = fmaxf(fmaxf(fmaxf(v0.x, v0.y), fmaxf(v0.z, v0.w)),
                    fmaxf(fmaxf(v1.x, v1.y), fmaxf(v1.z, v1.w)));
#pragma unroll
    for (int o = 16; o; o >>= 1) m = fmaxf(m, __shfl_xor_sync(0xffffffffu, m, o));

    __shared__ float smax[8];
    __shared__ float ssum[8];
    const int w = tid >> 5, lane = tid & 31;
    if (lane == 0) smax[w] = m;
    __syncthreads();
    float mm = smax[0];
#pragma unroll
    for (int i = 1; i < 8; i++) mm = fmaxf(mm, smax[i]);

    v0.x = __expf(v0.x - mm); v0.y = __expf(v0.y - mm);
    v0.z = __expf(v0.z - mm); v0.w = __expf(v0.w - mm);
    v1.x = __expf(v1.x - mm); v1.y = __expf(v1.y - mm);
    v1.z = __expf(v1.z - mm); v1.w = __expf(v1.w - mm);

    float s = (v0.x + v0.y + v0.z + v0.w) + (v1.x + v1.y + v1.z + v1.w);
#pragma unroll
    for (int o = 16; o; o >>= 1) s += __shfl_xor_sync(0xffffffffu, s, o);
    if (lane == 0) ssum[w] = s;
    __syncthreads();
    float ss = ssum[0];
#pragma unroll
    for (int i = 1; i < 8; i++) ss += ssum[i];
    float inv = __frcp_rn(ss);

    float4 h0, l0, h1, l1;
    split_f(v0.x * inv, h0.x, l0.x); split_f(v0.y * inv, h0.y, l0.y);
    split_f(v0.z * inv, h0.z, l0.z); split_f(v0.w * inv, h0.w, l0.w);
    split_f(v1.x * inv, h1.x, l1.x); split_f(v1.y * inv, h1.y, l1.y);
    split_f(v1.z * inv, h1.z, l1.z); split_f(v1.w * inv, h1.w, l1.w);
    p4[tid] = h0;
    p4[tid + 256] = h1;
    pl4[tid] = l0;
    pl4[tid + 256] = l1;
}

// ---------------- launch ----------------
extern "C" void kernel_launch(void* const* d_in, const int* in_sizes, int n_in,
                              void* d_out, int out_size)
{
    const float* x = (const float*)d_in[0];  // [B, S, D]
    const float* W = (const float*)d_in[1];  // [D, D]
    float* out = (float*)d_out;              // [B, S, D]

    float *xh, *xl, *xwh, *xwl, *prod, *plo, *wth, *wtl, *xth, *xtl;
    cudaGetSymbolAddress((void**)&xh, g_xh);
    cudaGetSymbolAddress((void**)&xl, g_xl);
    cudaGetSymbolAddress((void**)&xwh, g_xwh);
    cudaGetSymbolAddress((void**)&xwl, g_xwl);
    cudaGetSymbolAddress((void**)&prod, g_prod);
    cudaGetSymbolAddress((void**)&plo, g_plo);
    cudaGetSymbolAddress((void**)&wth, g_wth);
    cudaGetSymbolAddress((void**)&wtl, g_wtl);
    cudaGetSymbolAddress((void**)&xth, g_xth);
    cudaGetSymbolAddress((void**)&xtl, g_xtl);

    cudaFuncSetAttribute(tf32seg_gemm_nt, cudaFuncAttributeMaxDynamicSharedMemorySize, GEMM_SMEM);

    const float inv_sqrt_d = 0.04419417382415922f;  // 1/sqrt(512)

    // pre-split operands
    split_kernel<<<(BATCH * SEQ * DIM) / (256 * 4), 256>>>(x, xh, xl);
    transpose_split_kernel<<<dim3(DIM / 32, DIM / 32, 1), dim3(32, 8)>>>(W, wth, wtl, DIM, DIM);
    transpose_split_kernel<<<dim3(DIM / 32, SEQ / 32, BATCH), dim3(32, 8)>>>(x, xth, xtl, SEQ, DIM);

    // GEMM1: xw = x @ W^T'   M=16384, N=512, K=512 (ksh=4) ; epilogue splits xw -> hi/lo
    tf32seg_gemm_nt<<<dim3(DIM / BN, (BATCH * SEQ) / BM, 1), 256, GEMM_SMEM>>>(
        xh, xl, wth, wtl, xwh, xwl,
        BATCH * SEQ, DIM, DIM, 4, 0, 0, 0, 1.0f);

    // GEMM2: prod[b] = (xw[b] @ x[b]^T) / sqrt(D)   M=N=2048, K=512 (ksh=4)
    tf32seg_gemm_nt<<<dim3(SEQ / BN, SEQ / BM, BATCH), 256, GEMM_SMEM>>>(
        xwh, xwl, xh, xl, prod, nullptr,
        SEQ, SEQ, DIM, 4,
        (long long)SEQ * DIM, (long long)SEQ * DIM, (long long)SEQ * SEQ, inv_sqrt_d);

    // softmax rows: writes P_hi (in place) + P_lo
    softmax2048_kernel<<<BATCH * SEQ, 256>>>(prod, plo);

    // GEMM3: out[b] = P[b] @ x[b]   M=2048, N=512, K=2048 (ksh=6)
    tf32seg_gemm_nt<<<dim3(DIM / BN, SEQ / BM, BATCH), 256, GEMM_SMEM>>>(
        prod, plo, xth, xtl, out, nullptr,
        SEQ, DIM, SEQ, 6,
        (long long)SEQ * SEQ, (long long)SEQ * DIM, (long long)SEQ * DIM, 1.0f);
}